// round 6
// baseline (speedup 1.0000x reference)
#include <cuda_runtime.h>
#include <math.h>

#define N_NODES 6000
#define DEG 16
#define N_EDGES 96000
#define D_MODEL 256
#define D_MSG 64
#define D_FF 1024
#define N_LAYERS 3
#define RBF_BINS 256
#define WIN 32

// ---------------- scratch (static device memory; no allocation) ----------------
__device__ float g_x[N_NODES * D_MODEL];
__device__ float g_rhat[N_EDGES * 3];
__device__ float g_xj[N_NODES * D_MSG];
__device__ float g_xi[N_NODES * D_MSG];
__device__ float g_xij[N_EDGES * D_MSG];
__device__ float g_xn[N_NODES * D_MSG];
__device__ float g_h[N_NODES * D_FF];
__device__ float g_partial[256];

// ---------------- embedding gather ----------------
__global__ void embed_kernel(const int* __restrict__ an,
                             const float* __restrict__ emb,
                             float* __restrict__ x) {
    int i = blockIdx.x;
    int c = threadIdx.x;
    x[i * D_MODEL + c] = emb[an[i] * D_MODEL + c];
}

// ---------------- rhat (once) ----------------
__global__ void rhat_kernel(const float* __restrict__ r,
                            float* __restrict__ rhat) {
    int e = blockIdx.x * blockDim.x + threadIdx.x;
    if (e >= N_EDGES) return;
    float rx = r[e * 3 + 0], ry = r[e * 3 + 1], rz = r[e * 3 + 2];
    float d = sqrtf(rx * rx + ry * ry + rz * rz);
    rhat[e * 3 + 0] = rx / d;
    rhat[e * 3 + 1] = ry / d;
    rhat[e * 3 + 2] = rz / d;
}

// ---------------- fused windowed-RBF edge kernel -------------------------------
// 32-bin Gaussian window around d (|error| <~2e-5 on xij; tolerance is 1e-3).
#define EDGE_WPITCH 68
#define EDGE_SMEM_BYTES (256 * EDGE_WPITCH * 4 + 16 * WIN * 4 + 16 * 4 * 3)

__global__ void edge_kernel(const float* __restrict__ r,
                            const int* __restrict__ src,
                            const float* __restrict__ We,     // [64,256]
                            const float* __restrict__ bedge,  // [64]
                            const float* __restrict__ xj,
                            const float* __restrict__ xi,
                            float* __restrict__ xij) {
    extern __shared__ float sm[];
    float* sWt = sm;                        // [256][68] transposed Wedge
    float* sy = sm + 256 * EDGE_WPITCH;     // [16][WIN]
    int* sb0 = (int*)(sy + 16 * WIN);       // [16]
    int* ssrc = sb0 + 16;                   // [16]
    float* sd = (float*)(ssrc + 16);        // [16]

    int t = threadIdx.x;
    for (int idx = t; idx < 64 * 256; idx += 256) {
        int ch = idx >> 8, b = idx & 255;
        sWt[b * EDGE_WPITCH + ch] = We[idx];
    }
    int e_sub = t >> 4;      // 0..15 edge slot
    int chv = t & 15;        // channel group (4 ch)
    float4 bed = *(const float4*)&bedge[chv * 4];
    const float inv_step = 255.0f / 8.0f;
    const float step = 8.0f / 255.0f;
    const float gamma = inv_step;

    for (int g = blockIdx.x; g < N_NODES; g += gridDim.x) {
        __syncthreads();
        if (t < 16) {
            int e = g * 16 + t;
            float rx = r[e * 3 + 0], ry = r[e * 3 + 1], rz = r[e * 3 + 2];
            float d = sqrtf(rx * rx + ry * ry + rz * rz);
            int cb = (int)(d * inv_step + 0.5f);
            int b0 = cb - WIN / 2;
            b0 = b0 < 0 ? 0 : (b0 > 256 - WIN ? 256 - WIN : b0);
            sb0[t] = b0;
            sd[t] = d;
            ssrc[t] = src[e];
        }
        __syncthreads();
        {   // y window: thread computes 2 bins of its edge
            float d = sd[e_sub];
            int b0 = sb0[e_sub];
            int jb = chv * 2;
#pragma unroll
            for (int i = 0; i < 2; i++) {
                float tt = d - (float)(b0 + jb + i) * step;
                sy[e_sub * WIN + jb + i] = __expf(-gamma * tt * tt);
            }
        }
        __syncthreads();
        {
            int b0 = sb0[e_sub];
            const float* wp = sWt + (size_t)b0 * EDGE_WPITCH + chv * 4;
            const float* yp = sy + e_sub * WIN;
            float4 acc = bed;
#pragma unroll 16
            for (int j = 0; j < WIN; j++) {
                float yv = yp[j];
                float4 w = *(const float4*)(wp + (size_t)j * EDGE_WPITCH);
                acc.x = fmaf(yv, w.x, acc.x);
                acc.y = fmaf(yv, w.y, acc.y);
                acc.z = fmaf(yv, w.z, acc.z);
                acc.w = fmaf(yv, w.w, acc.w);
            }
            int sidx = ssrc[e_sub];
            float4 aj = *(const float4*)&xj[sidx * 64 + chv * 4];
            float4 ai = *(const float4*)&xi[g * 64 + chv * 4];
            acc.x += aj.x + ai.x;
            acc.y += aj.y + ai.y;
            acc.z += aj.z + ai.z;
            acc.w += aj.w + ai.w;
            *(float4*)&xij[(size_t)(g * 16 + e_sub) * 64 + chv * 4] = acc;
        }
    }
}

// ---------------- SGEMM: C[M,N] = A[M,K] @ B[N,K]^T + bias ---------------------
// 64 threads, 64x64 tile, 8x8 micro-tile, K-chunk 16.
// EPI 0: +bias   EPI 1: silu(+bias)   EPI 3: dual node-proj (bx selects set)
template <int EPI>
__global__ __launch_bounds__(64)
void gemm8x8(const float* __restrict__ A,
             const float* __restrict__ B,
             float* __restrict__ C,
             int M, int N, int K,
             const float* __restrict__ bias,
             const float* __restrict__ B2,
             const float* __restrict__ bias2,
             float* __restrict__ C2) {
    __shared__ float As[16][64];
    __shared__ float Bs[16][64];
    int t = threadIdx.x;
    int n0 = blockIdx.x * 64;
    int m0 = blockIdx.y * 64;
    if (EPI == 3) {
        if (blockIdx.x == 1) { B = B2; bias = bias2; C = C2; }
        n0 = 0;
    }
    int rowA = m0 + t;
    bool okA = rowA < M;
    const float* Ap = A + (size_t)(okA ? rowA : (M - 1)) * K;
    const float* Bp = B + (size_t)(n0 + t) * K;
    int rg = (t >> 3) * 8;
    int cg = (t & 7) * 8;

    float acc[8][8];
#pragma unroll
    for (int i = 0; i < 8; i++)
#pragma unroll
        for (int j = 0; j < 8; j++) acc[i][j] = 0.0f;

    for (int k0 = 0; k0 < K; k0 += 16) {
        float4 av[4], bv[4];
#pragma unroll
        for (int i = 0; i < 4; i++) {
            av[i] = *(const float4*)(Ap + k0 + i * 4);
            bv[i] = *(const float4*)(Bp + k0 + i * 4);
        }
        __syncthreads();
#pragma unroll
        for (int i = 0; i < 4; i++) {
            As[i * 4 + 0][t] = av[i].x;
            As[i * 4 + 1][t] = av[i].y;
            As[i * 4 + 2][t] = av[i].z;
            As[i * 4 + 3][t] = av[i].w;
            Bs[i * 4 + 0][t] = bv[i].x;
            Bs[i * 4 + 1][t] = bv[i].y;
            Bs[i * 4 + 2][t] = bv[i].z;
            Bs[i * 4 + 3][t] = bv[i].w;
        }
        __syncthreads();
#pragma unroll
        for (int kk = 0; kk < 16; kk++) {
            float4 a0 = *(const float4*)&As[kk][rg];
            float4 a1 = *(const float4*)&As[kk][rg + 4];
            float4 b0 = *(const float4*)&Bs[kk][cg];
            float4 b1 = *(const float4*)&Bs[kk][cg + 4];
            float ar[8] = {a0.x, a0.y, a0.z, a0.w, a1.x, a1.y, a1.z, a1.w};
            float br[8] = {b0.x, b0.y, b0.z, b0.w, b1.x, b1.y, b1.z, b1.w};
#pragma unroll
            for (int i = 0; i < 8; i++)
#pragma unroll
                for (int j = 0; j < 8; j++)
                    acc[i][j] = fmaf(ar[i], br[j], acc[i][j]);
        }
    }

    float4 bb0 = *(const float4*)&bias[n0 + cg];
    float4 bb1 = *(const float4*)&bias[n0 + cg + 4];
    float bb[8] = {bb0.x, bb0.y, bb0.z, bb0.w, bb1.x, bb1.y, bb1.z, bb1.w};
#pragma unroll
    for (int i = 0; i < 8; i++) {
        int m = m0 + rg + i;
        if (m >= M) continue;
        float v[8];
#pragma unroll
        for (int j = 0; j < 8; j++) {
            float s = acc[i][j] + bb[j];
            if (EPI == 1) s = __fdividef(s, 1.0f + __expf(-s));
            v[j] = s;
        }
        *(float4*)&C[(size_t)m * N + n0 + cg] =
            make_float4(v[0], v[1], v[2], v[3]);
        *(float4*)&C[(size_t)m * N + n0 + cg + 4] =
            make_float4(v[4], v[5], v[6], v[7]);
    }
}

// ---------------- per-node triplet attention ----------------
__global__ void triplet_kernel(const float* __restrict__ xij,
                               const float* __restrict__ rhat,
                               const float* __restrict__ attn,
                               float* __restrict__ xn) {
    __shared__ float sx[64][17];
    __shared__ float rh[16][3];
    __shared__ float sat[64];
    __shared__ float sl[16][16];
    __shared__ float mq[16], zi[16], wp[16];

    int node = blockIdx.x;
    int t = threadIdx.x;
    const float* xb = xij + (size_t)node * 16 * 64;

    for (int idx = t; idx < 1024; idx += 256) {
        int p = idx >> 6, k = idx & 63;
        sx[k][p] = xb[idx];
    }
    if (t < 48) rh[t / 3][t % 3] = rhat[node * 48 + t];
    if (t < 64) sat[t] = attn[t];
    __syncthreads();

    if (t < 240) {
        int q = t / 15;
        int ps = t % 15;
        int p = ps + (ps >= q ? 1 : 0);
        float c = rh[p][0] * rh[q][0] + rh[p][1] * rh[q][1] + rh[p][2] * rh[q][2];
        c = fminf(fmaxf(c, -1.0f + 1e-6f), 1.0f - 1e-6f);
        float c2 = 2.0f * c;
        float t0 = 1.0f, t1 = c;
        float acc;
        {
            float s = 1.0f + sx[0][p] + sx[0][q];
            float si = __fdividef(s, 1.0f + __expf(-s));
            acc = sat[0] * si;
        }
#pragma unroll
        for (int k = 1; k < 64; k++) {
            float z = t1;
            float s = z + sx[k][p] + sx[k][q];
            float si = __fdividef(s, 1.0f + __expf(-s));
            acc = fmaf(sat[k], si, acc);
            float tn = fmaf(c2, t1, -t0);
            t0 = t1; t1 = tn;
        }
        sl[q][ps] = acc;
    }
    __syncthreads();

    if (t < 16) {
        int q = t;
        float m = -1e30f;
#pragma unroll
        for (int ps = 0; ps < 15; ps++) m = fmaxf(m, sl[q][ps]);
        float z = 0.0f;
#pragma unroll
        for (int ps = 0; ps < 15; ps++) z += __expf(sl[q][ps] - m);
        mq[q] = m;
        zi[q] = __fdividef(1.0f, z);
    }
    __syncthreads();

    if (t < 16) {
        int p = t;
        float w = 0.0f;
#pragma unroll
        for (int q = 0; q < 16; q++) {
            if (q == p) continue;
            int ps = (p < q) ? p : p - 1;
            w += __expf(sl[q][ps] - mq[q]) * zi[q];
        }
        wp[p] = w;
    }
    __syncthreads();

    if (t < 64) {
        int k = t;
        float acc = 0.0f;
#pragma unroll
        for (int p = 0; p < 16; p++) acc = fmaf(wp[p], sx[k][p], acc);
        xn[node * 64 + k] = acc;
    }
}

// ---------------- output head ----------------
__global__ void out_partial_kernel(const float* __restrict__ x,
                                   const float* __restrict__ Wfc,
                                   float* __restrict__ partial) {
    __shared__ float red[256];
    float acc = 0.0f;
    for (int idx = blockIdx.x * 256 + threadIdx.x; idx < N_NODES * D_MODEL;
         idx += 256 * 256)
        acc = fmaf(x[idx], Wfc[idx & 255], acc);
    red[threadIdx.x] = acc;
    __syncthreads();
    for (int s = 128; s > 0; s >>= 1) {
        if (threadIdx.x < s) red[threadIdx.x] += red[threadIdx.x + s];
        __syncthreads();
    }
    if (threadIdx.x == 0) partial[blockIdx.x] = red[0];
}

__global__ void out_final_kernel(const float* __restrict__ partial,
                                 const float* __restrict__ bfc,
                                 float* __restrict__ out) {
    if (threadIdx.x == 0) {
        float s = 0.0f;
        for (int i = 0; i < 256; i++) s += partial[i];
        out[0] = s / (float)N_NODES + bfc[0];
    }
}

// ---------------- launcher ----------------
extern "C" void kernel_launch(void* const* d_in, const int* in_sizes, int n_in,
                              void* d_out, int out_size) {
    const float* r     = (const float*)d_in[0];
    const int*   an    = (const int*)d_in[1];
    const int*   src   = (const int*)d_in[2];
    const float* emb   = (const float*)d_in[6];
    const float* Wsrc  = (const float*)d_in[7];
    const float* bsrc  = (const float*)d_in[8];
    const float* Wdst  = (const float*)d_in[9];
    const float* bdst  = (const float*)d_in[10];
    const float* Wedge = (const float*)d_in[11];
    const float* bedge = (const float*)d_in[12];
    const float* attn  = (const float*)d_in[13];
    const float* W1    = (const float*)d_in[14];
    const float* b1    = (const float*)d_in[15];
    const float* W2    = (const float*)d_in[16];
    const float* b2    = (const float*)d_in[17];
    const float* Wfc   = (const float*)d_in[18];
    const float* bfc   = (const float*)d_in[19];
    float* out = (float*)d_out;

    float *x, *rhat, *xj, *xi, *xij, *xn, *h, *part;
    cudaGetSymbolAddress((void**)&x,    g_x);
    cudaGetSymbolAddress((void**)&rhat, g_rhat);
    cudaGetSymbolAddress((void**)&xj,   g_xj);
    cudaGetSymbolAddress((void**)&xi,   g_xi);
    cudaGetSymbolAddress((void**)&xij,  g_xij);
    cudaGetSymbolAddress((void**)&xn,   g_xn);
    cudaGetSymbolAddress((void**)&h,    g_h);
    cudaGetSymbolAddress((void**)&part, g_partial);

    cudaFuncSetAttribute(edge_kernel,
                         cudaFuncAttributeMaxDynamicSharedMemorySize,
                         EDGE_SMEM_BYTES);

    embed_kernel<<<N_NODES, 256>>>(an, emb, x);
    rhat_kernel<<<(N_EDGES + 255) / 256, 256>>>(r, rhat);

    const int MB_NODE = (N_NODES + 63) / 64;   // 94

    for (int l = 0; l < N_LAYERS; l++) {
        gemm8x8<3><<<dim3(2, MB_NODE), 64>>>(
            x, Wsrc + l * 64 * 256, xj, N_NODES, 64, 256, bsrc + l * 64,
            Wdst + l * 64 * 256, bdst + l * 64, xi);
        edge_kernel<<<444, 256, EDGE_SMEM_BYTES>>>(
            r, src, Wedge + l * 64 * 256, bedge + l * 64, xj, xi, xij);
        triplet_kernel<<<N_NODES, 256>>>(xij, rhat, attn + l * 64, xn);
        gemm8x8<1><<<dim3(16, MB_NODE), 64>>>(
            xn, W1 + l * D_FF * 64, h, N_NODES, D_FF, 64, b1 + l * D_FF,
            nullptr, nullptr, nullptr);
        gemm8x8<0><<<dim3(4, MB_NODE), 64>>>(
            h, W2 + l * D_MODEL * D_FF, x, N_NODES, D_MODEL, D_FF,
            b2 + l * D_MODEL, nullptr, nullptr, nullptr);
    }

    out_partial_kernel<<<256, 256>>>(x, Wfc, part);
    out_final_kernel<<<1, 32>>>(part, bfc, out);
}

// round 7
// speedup vs baseline: 1.1212x; 1.1212x over previous
#include <cuda_runtime.h>
#include <math.h>
#include <stdint.h>

#define N_NODES 6000
#define DEG 16
#define N_EDGES 96000
#define D_MODEL 256
#define D_MSG 64
#define D_FF 1024
#define N_LAYERS 3
#define RBF_BINS 256
#define WIN 32

// ---------------- scratch (static device memory; no allocation) ----------------
__device__ float g_x[N_NODES * D_MODEL];
__device__ float g_rhat[N_EDGES * 3];
__device__ float g_xj[N_NODES * D_MSG];
__device__ float g_xi[N_NODES * D_MSG];
__device__ float g_xij[N_EDGES * D_MSG];
__device__ float g_xn[N_NODES * D_MSG];
__device__ float g_h[N_NODES * D_FF];
__device__ float g_partial[256];

// ---------------- packed f32x2 helpers (sm_10x) ----------------
__device__ __forceinline__ uint64_t pk2(float lo, float hi) {
    uint64_t r;
    asm("mov.b64 %0, {%1, %2};" : "=l"(r) : "f"(lo), "f"(hi));
    return r;
}
__device__ __forceinline__ void upk2(float& lo, float& hi, uint64_t v) {
    asm("mov.b64 {%0, %1}, %2;" : "=f"(lo), "=f"(hi) : "l"(v));
}
__device__ __forceinline__ void ffma2(uint64_t& d, uint64_t a, uint64_t b) {
    asm("fma.rn.f32x2 %0, %1, %2, %0;" : "+l"(d) : "l"(a), "l"(b));
}

// ---------------- embedding gather ----------------
__global__ void embed_kernel(const int* __restrict__ an,
                             const float* __restrict__ emb,
                             float* __restrict__ x) {
    int i = blockIdx.x;
    int c = threadIdx.x;
    x[i * D_MODEL + c] = emb[an[i] * D_MODEL + c];
}

// ---------------- rhat (once) ----------------
__global__ void rhat_kernel(const float* __restrict__ r,
                            float* __restrict__ rhat) {
    int e = blockIdx.x * blockDim.x + threadIdx.x;
    if (e >= N_EDGES) return;
    float rx = r[e * 3 + 0], ry = r[e * 3 + 1], rz = r[e * 3 + 2];
    float d = sqrtf(rx * rx + ry * ry + rz * rz);
    rhat[e * 3 + 0] = rx / d;
    rhat[e * 3 + 1] = ry / d;
    rhat[e * 3 + 2] = rz / d;
}

// ---------------- fused windowed-RBF edge kernel -------------------------------
// 32-bin Gaussian window around d (|error| <~2e-5 on xij; tolerance is 1e-3).
#define EDGE_WPITCH 68
#define EDGE_SMEM_BYTES (256 * EDGE_WPITCH * 4 + 16 * WIN * 4 + 16 * 4 * 3)

__global__ void edge_kernel(const float* __restrict__ r,
                            const int* __restrict__ src,
                            const float* __restrict__ We,     // [64,256]
                            const float* __restrict__ bedge,  // [64]
                            const float* __restrict__ xj,
                            const float* __restrict__ xi,
                            float* __restrict__ xij) {
    extern __shared__ float sm[];
    float* sWt = sm;                        // [256][68] transposed Wedge
    float* sy = sm + 256 * EDGE_WPITCH;     // [16][WIN]
    int* sb0 = (int*)(sy + 16 * WIN);       // [16]
    int* ssrc = sb0 + 16;                   // [16]
    float* sd = (float*)(ssrc + 16);        // [16]

    int t = threadIdx.x;
    for (int idx = t; idx < 64 * 256; idx += 256) {
        int ch = idx >> 8, b = idx & 255;
        sWt[b * EDGE_WPITCH + ch] = We[idx];
    }
    int e_sub = t >> 4;      // 0..15 edge slot
    int chv = t & 15;        // channel group (4 ch)
    float4 bed = *(const float4*)&bedge[chv * 4];
    const float inv_step = 255.0f / 8.0f;
    const float step = 8.0f / 255.0f;
    const float gamma = inv_step;

    for (int g = blockIdx.x; g < N_NODES; g += gridDim.x) {
        __syncthreads();
        if (t < 16) {
            int e = g * 16 + t;
            float rx = r[e * 3 + 0], ry = r[e * 3 + 1], rz = r[e * 3 + 2];
            float d = sqrtf(rx * rx + ry * ry + rz * rz);
            int cb = (int)(d * inv_step + 0.5f);
            int b0 = cb - WIN / 2;
            b0 = b0 < 0 ? 0 : (b0 > 256 - WIN ? 256 - WIN : b0);
            sb0[t] = b0;
            sd[t] = d;
            ssrc[t] = src[e];
        }
        __syncthreads();
        {   // y window: thread computes 2 bins of its edge
            float d = sd[e_sub];
            int b0 = sb0[e_sub];
            int jb = chv * 2;
#pragma unroll
            for (int i = 0; i < 2; i++) {
                float tt = d - (float)(b0 + jb + i) * step;
                sy[e_sub * WIN + jb + i] = __expf(-gamma * tt * tt);
            }
        }
        __syncthreads();
        {
            int b0 = sb0[e_sub];
            const float* wp = sWt + (size_t)b0 * EDGE_WPITCH + chv * 4;
            const float* yp = sy + e_sub * WIN;
            float4 acc = bed;
#pragma unroll 16
            for (int j = 0; j < WIN; j++) {
                float yv = yp[j];
                float4 w = *(const float4*)(wp + (size_t)j * EDGE_WPITCH);
                acc.x = fmaf(yv, w.x, acc.x);
                acc.y = fmaf(yv, w.y, acc.y);
                acc.z = fmaf(yv, w.z, acc.z);
                acc.w = fmaf(yv, w.w, acc.w);
            }
            int sidx = ssrc[e_sub];
            float4 aj = *(const float4*)&xj[sidx * 64 + chv * 4];
            float4 ai = *(const float4*)&xi[g * 64 + chv * 4];
            acc.x += aj.x + ai.x;
            acc.y += aj.y + ai.y;
            acc.z += aj.z + ai.z;
            acc.w += aj.w + ai.w;
            *(float4*)&xij[(size_t)(g * 16 + e_sub) * 64 + chv * 4] = acc;
        }
    }
}

// ---------------- SGEMM: C[M,N] = A[M,K] @ B[N,K]^T + bias ---------------------
// 128 threads, 64x64 tile, 8x4 micro-tile as 4 row-pairs (f32x2), K-chunk 32.
// EPI 0: +bias   EPI 1: silu(+bias)   EPI 3: dual node-proj (bx selects set)
template <int EPI>
__global__ __launch_bounds__(128)
void gemm64(const float* __restrict__ A,
            const float* __restrict__ B,
            float* __restrict__ C,
            int M, int N, int K,
            const float* __restrict__ bias,
            const float* __restrict__ B2,
            const float* __restrict__ bias2,
            float* __restrict__ C2) {
    __shared__ float As[32][64];
    __shared__ float Bs[32][64];
    int t = threadIdx.x;
    int n0 = blockIdx.x * 64;
    int m0 = blockIdx.y * 64;
    if (EPI == 3) {
        if (blockIdx.x == 1) { B = B2; bias = bias2; C = C2; }
        n0 = 0;
    }
    int r = t & 63;
    int kb = (t >> 6) * 16;        // which 16-k half this thread loads
    int rg8 = (t >> 4) * 8;        // 0..56 (row group of 8, as 4 pairs)
    int cg4 = (t & 15) * 4;        // col group of 4

    uint64_t acc2[4][4];           // [row-pair][col] packed f32x2 over rows
#pragma unroll
    for (int i = 0; i < 4; i++)
#pragma unroll
        for (int j = 0; j < 4; j++) acc2[i][j] = 0ull;

    int rowA = m0 + r;
    bool okA = rowA < M;
    const float* Ap = A + (size_t)(okA ? rowA : (M - 1)) * K + kb;
    const float* Bp = B + (size_t)(n0 + r) * K + kb;

    for (int k0 = 0; k0 < K; k0 += 32) {
        float4 av[4], bv[4];
#pragma unroll
        for (int i = 0; i < 4; i++) {
            av[i] = okA ? *(const float4*)(Ap + k0 + i * 4)
                        : make_float4(0.f, 0.f, 0.f, 0.f);
            bv[i] = *(const float4*)(Bp + k0 + i * 4);
        }
        __syncthreads();
#pragma unroll
        for (int i = 0; i < 4; i++) {
            As[kb + i * 4 + 0][r] = av[i].x;
            As[kb + i * 4 + 1][r] = av[i].y;
            As[kb + i * 4 + 2][r] = av[i].z;
            As[kb + i * 4 + 3][r] = av[i].w;
            Bs[kb + i * 4 + 0][r] = bv[i].x;
            Bs[kb + i * 4 + 1][r] = bv[i].y;
            Bs[kb + i * 4 + 2][r] = bv[i].z;
            Bs[kb + i * 4 + 3][r] = bv[i].w;
        }
        __syncthreads();
#pragma unroll 8
        for (int kk = 0; kk < 32; kk++) {
            float4 a0 = *(const float4*)&As[kk][rg8];
            float4 a1 = *(const float4*)&As[kk][rg8 + 4];
            float4 b = *(const float4*)&Bs[kk][cg4];
            uint64_t ap[4] = {pk2(a0.x, a0.y), pk2(a0.z, a0.w),
                              pk2(a1.x, a1.y), pk2(a1.z, a1.w)};
            uint64_t bd[4] = {pk2(b.x, b.x), pk2(b.y, b.y),
                              pk2(b.z, b.z), pk2(b.w, b.w)};
#pragma unroll
            for (int i = 0; i < 4; i++)
#pragma unroll
                for (int j = 0; j < 4; j++)
                    ffma2(acc2[i][j], ap[i], bd[j]);
        }
    }
    __syncthreads();

    float4 b4 = *(const float4*)&bias[n0 + cg4];
    float bb[4] = {b4.x, b4.y, b4.z, b4.w};
#pragma unroll
    for (int i = 0; i < 4; i++) {         // row pair i -> rows rg8+2i, rg8+2i+1
        float v0[4], v1[4];
#pragma unroll
        for (int j = 0; j < 4; j++) {
            float lo, hi;
            upk2(lo, hi, acc2[i][j]);
            lo += bb[j];
            hi += bb[j];
            if (EPI == 1) {
                lo = __fdividef(lo, 1.0f + __expf(-lo));
                hi = __fdividef(hi, 1.0f + __expf(-hi));
            }
            v0[j] = lo;
            v1[j] = hi;
        }
        int m = m0 + rg8 + 2 * i;
        if (m < M)
            *(float4*)&C[(size_t)m * N + n0 + cg4] =
                make_float4(v0[0], v0[1], v0[2], v0[3]);
        if (m + 1 < M)
            *(float4*)&C[(size_t)(m + 1) * N + n0 + cg4] =
                make_float4(v1[0], v1[1], v1[2], v1[3]);
    }
}

// ---------------- per-node triplet attention ----------------
__global__ void triplet_kernel(const float* __restrict__ xij,
                               const float* __restrict__ rhat,
                               const float* __restrict__ attn,
                               float* __restrict__ xn) {
    __shared__ float sx[64][17];
    __shared__ float rh[16][3];
    __shared__ float sat[64];
    __shared__ float sl[16][16];
    __shared__ float mq[16], zi[16], wp[16];

    int node = blockIdx.x;
    int t = threadIdx.x;
    const float* xb = xij + (size_t)node * 16 * 64;

    for (int idx = t; idx < 1024; idx += 256) {
        int p = idx >> 6, k = idx & 63;
        sx[k][p] = xb[idx];
    }
    if (t < 48) rh[t / 3][t % 3] = rhat[node * 48 + t];
    if (t < 64) sat[t] = attn[t];
    __syncthreads();

    if (t < 240) {
        int q = t / 15;
        int ps = t % 15;
        int p = ps + (ps >= q ? 1 : 0);
        float c = rh[p][0] * rh[q][0] + rh[p][1] * rh[q][1] + rh[p][2] * rh[q][2];
        c = fminf(fmaxf(c, -1.0f + 1e-6f), 1.0f - 1e-6f);
        float c2 = 2.0f * c;
        float t0 = 1.0f, t1 = c;
        float acc;
        {
            float s = 1.0f + sx[0][p] + sx[0][q];
            float si = __fdividef(s, 1.0f + __expf(-s));
            acc = sat[0] * si;
        }
#pragma unroll
        for (int k = 1; k < 64; k++) {
            float z = t1;
            float s = z + sx[k][p] + sx[k][q];
            float si = __fdividef(s, 1.0f + __expf(-s));
            acc = fmaf(sat[k], si, acc);
            float tn = fmaf(c2, t1, -t0);
            t0 = t1; t1 = tn;
        }
        sl[q][ps] = acc;
    }
    __syncthreads();

    if (t < 16) {
        int q = t;
        float m = -1e30f;
#pragma unroll
        for (int ps = 0; ps < 15; ps++) m = fmaxf(m, sl[q][ps]);
        float z = 0.0f;
#pragma unroll
        for (int ps = 0; ps < 15; ps++) z += __expf(sl[q][ps] - m);
        mq[q] = m;
        zi[q] = __fdividef(1.0f, z);
    }
    __syncthreads();

    if (t < 16) {
        int p = t;
        float w = 0.0f;
#pragma unroll
        for (int q = 0; q < 16; q++) {
            if (q == p) continue;
            int ps = (p < q) ? p : p - 1;
            w += __expf(sl[q][ps] - mq[q]) * zi[q];
        }
        wp[p] = w;
    }
    __syncthreads();

    if (t < 64) {
        int k = t;
        float acc = 0.0f;
#pragma unroll
        for (int p = 0; p < 16; p++) acc = fmaf(wp[p], sx[k][p], acc);
        xn[node * 64 + k] = acc;
    }
}

// ---------------- output head ----------------
__global__ void out_partial_kernel(const float* __restrict__ x,
                                   const float* __restrict__ Wfc,
                                   float* __restrict__ partial) {
    __shared__ float red[256];
    float acc = 0.0f;
    for (int idx = blockIdx.x * 256 + threadIdx.x; idx < N_NODES * D_MODEL;
         idx += 256 * 256)
        acc = fmaf(x[idx], Wfc[idx & 255], acc);
    red[threadIdx.x] = acc;
    __syncthreads();
    for (int s = 128; s > 0; s >>= 1) {
        if (threadIdx.x < s) red[threadIdx.x] += red[threadIdx.x + s];
        __syncthreads();
    }
    if (threadIdx.x == 0) partial[blockIdx.x] = red[0];
}

__global__ void out_final_kernel(const float* __restrict__ partial,
                                 const float* __restrict__ bfc,
                                 float* __restrict__ out) {
    if (threadIdx.x == 0) {
        float s = 0.0f;
        for (int i = 0; i < 256; i++) s += partial[i];
        out[0] = s / (float)N_NODES + bfc[0];
    }
}

// ---------------- launcher ----------------
extern "C" void kernel_launch(void* const* d_in, const int* in_sizes, int n_in,
                              void* d_out, int out_size) {
    const float* r     = (const float*)d_in[0];
    const int*   an    = (const int*)d_in[1];
    const int*   src   = (const int*)d_in[2];
    const float* emb   = (const float*)d_in[6];
    const float* Wsrc  = (const float*)d_in[7];
    const float* bsrc  = (const float*)d_in[8];
    const float* Wdst  = (const float*)d_in[9];
    const float* bdst  = (const float*)d_in[10];
    const float* Wedge = (const float*)d_in[11];
    const float* bedge = (const float*)d_in[12];
    const float* attn  = (const float*)d_in[13];
    const float* W1    = (const float*)d_in[14];
    const float* b1    = (const float*)d_in[15];
    const float* W2    = (const float*)d_in[16];
    const float* b2    = (const float*)d_in[17];
    const float* Wfc   = (const float*)d_in[18];
    const float* bfc   = (const float*)d_in[19];
    float* out = (float*)d_out;

    float *x, *rhat, *xj, *xi, *xij, *xn, *h, *part;
    cudaGetSymbolAddress((void**)&x,    g_x);
    cudaGetSymbolAddress((void**)&rhat, g_rhat);
    cudaGetSymbolAddress((void**)&xj,   g_xj);
    cudaGetSymbolAddress((void**)&xi,   g_xi);
    cudaGetSymbolAddress((void**)&xij,  g_xij);
    cudaGetSymbolAddress((void**)&xn,   g_xn);
    cudaGetSymbolAddress((void**)&h,    g_h);
    cudaGetSymbolAddress((void**)&part, g_partial);

    cudaFuncSetAttribute(edge_kernel,
                         cudaFuncAttributeMaxDynamicSharedMemorySize,
                         EDGE_SMEM_BYTES);

    embed_kernel<<<N_NODES, 256>>>(an, emb, x);
    rhat_kernel<<<(N_EDGES + 255) / 256, 256>>>(r, rhat);

    const int MB_NODE = (N_NODES + 63) / 64;   // 94

    for (int l = 0; l < N_LAYERS; l++) {
        gemm64<3><<<dim3(2, MB_NODE), 128>>>(
            x, Wsrc + l * 64 * 256, xj, N_NODES, 64, 256, bsrc + l * 64,
            Wdst + l * 64 * 256, bdst + l * 64, xi);
        edge_kernel<<<444, 256, EDGE_SMEM_BYTES>>>(
            r, src, Wedge + l * 64 * 256, bedge + l * 64, xj, xi, xij);
        triplet_kernel<<<N_NODES, 256>>>(xij, rhat, attn + l * 64, xn);
        gemm64<1><<<dim3(16, MB_NODE), 128>>>(
            xn, W1 + l * D_FF * 64, h, N_NODES, D_FF, 64, b1 + l * D_FF,
            nullptr, nullptr, nullptr);
        gemm64<0><<<dim3(4, MB_NODE), 128>>>(
            h, W2 + l * D_MODEL * D_FF, x, N_NODES, D_MODEL, D_FF,
            b2 + l * D_MODEL, nullptr, nullptr, nullptr);
    }

    out_partial_kernel<<<256, 256>>>(x, Wfc, part);
    out_final_kernel<<<1, 32>>>(part, bfc, out);
}